// round 14
// baseline (speedup 1.0000x reference)
#include <cuda_runtime.h>

// ---------------------------------------------------------------------------
// LieSpline: SE(3) cubic B-spline.  B=32, N=2048, K=32.
//
// Kernel 1: per padded delta j: se3_log + exp precomputes + pose -> g_pre,
//   5 float4/record: r0=(tau|nd) r1=(U|C1'x) r2=(C1'y,C1'z,C2'x,C2'y)
//                    r3=(C2'z,pose_t) r4=pose_q
// Kernel 2 (packed f32x2 + dual chains):
//   warp = 4 consecutive segments.  half = lane>>4; thread chains:
//     Ta = segment s0+half,  Tb = segment s0+2+half   (independent -> ILP)
//   each lane evaluates samples (k, k+16), k = lane&15, packed in f32x2.
//   Records (6/warp, 30 float4) cooperatively loaded and stored DUPLICATED
//   (each scalar as (x,x) u64) so packed operands come straight from
//   LDS.128 (ulonglong2 = 2 dup-scalars per load) — no pack movs.
// ---------------------------------------------------------------------------

#define LS_B 32
#define LS_N 2048
#define LS_J (LS_N + 1)   // 2049 deltas per batch
#define REC 5             // float4s per record in g_pre
#define LS_S (LS_N - 1)   // 2047 segments
#define LS_M4 512         // segment-quads per batch

__device__ float4 g_pre[LS_B * LS_J * REC];   // 5.2 MB scratch

typedef unsigned long long u64;

__device__ __forceinline__ float3 f3(float x, float y, float z) {
    return make_float3(x, y, z);
}
__device__ __forceinline__ float3 cross3(const float3 a, const float3 b) {
    return make_float3(a.y * b.z - a.z * b.y,
                       a.z * b.x - a.x * b.z,
                       a.x * b.y - a.y * b.x);
}
__device__ __forceinline__ float dot3(const float3 a, const float3 b) {
    return a.x * b.x + a.y * b.y + a.z * b.z;
}
__device__ __forceinline__ float3 qrot(const float4 q, const float3 v) {
    float3 qv = f3(q.x, q.y, q.z);
    float3 t = cross3(qv, v);
    t.x *= 2.0f; t.y *= 2.0f; t.z *= 2.0f;
    float3 c = cross3(qv, t);
    return f3(v.x + q.w * t.x + c.x,
              v.y + q.w * t.y + c.y,
              v.z + q.w * t.z + c.z);
}
__device__ __forceinline__ float4 qmul(const float4 a, const float4 b) {
    return make_float4(
        a.w * b.x + a.x * b.w + a.y * b.z - a.z * b.y,
        a.w * b.y + a.y * b.w + a.z * b.x - a.x * b.z,
        a.w * b.z + a.z * b.w + a.x * b.y - a.y * b.x,
        a.w * b.w - a.x * b.x - a.y * b.y - a.z * b.z);
}

// ---------------- packed f32x2 helpers ----------------
__device__ __forceinline__ u64 pk2(float lo, float hi) {
    u64 r; asm("mov.b64 %0, {%1, %2};" : "=l"(r) : "f"(lo), "f"(hi)); return r;
}
__device__ __forceinline__ void unpk2(u64 v, float& lo, float& hi) {
    asm("mov.b64 {%0, %1}, %2;" : "=f"(lo), "=f"(hi) : "l"(v));
}
__device__ __forceinline__ u64 f2mul(u64 a, u64 b) {
    u64 r; asm("mul.rn.f32x2 %0, %1, %2;" : "=l"(r) : "l"(a), "l"(b)); return r;
}
__device__ __forceinline__ u64 f2add(u64 a, u64 b) {
    u64 r; asm("add.rn.f32x2 %0, %1, %2;" : "=l"(r) : "l"(a), "l"(b)); return r;
}
__device__ __forceinline__ u64 f2fma(u64 a, u64 b, u64 c) {
    u64 r; asm("fma.rn.f32x2 %0, %1, %2, %3;" : "=l"(r) : "l"(a), "l"(b), "l"(c)); return r;
}
__device__ __forceinline__ u64 f2neg(u64 a) { return a ^ 0x8000000080000000ULL; }

// ---------------------------------------------------------------------------
// Kernel 1: per-(b, j) relative-pose log + precompute
// ---------------------------------------------------------------------------
__global__ void __launch_bounds__(128) k_delta(const float* __restrict__ poses) {
    unsigned idx = blockIdx.x * blockDim.x + threadIdx.x;
    if (idx >= LS_B * LS_J) return;
    unsigned b = idx / LS_J;
    unsigned j = idx - b * LS_J;
    float4* o = g_pre + idx * REC;
    const float* pbase = poses + b * (LS_N * 7);

    unsigned pj = j > 0 ? j - 1 : 0;
    const float* pr = pbase + pj * 7;
    float3 t0 = f3(pr[0], pr[1], pr[2]);
    float4 q0 = make_float4(pr[3], pr[4], pr[5], pr[6]);
    o[4] = q0;

    if (j == 0 || j == LS_N) {
        float4 z = make_float4(0.f, 0.f, 0.f, 0.f);
        o[0] = z; o[1] = z; o[2] = z;
        o[3] = make_float4(0.f, t0.x, t0.y, t0.z);
        return;
    }
    const float* pr1 = pr + 7;
    float3 t1 = f3(pr1[0], pr1[1], pr1[2]);
    float4 q1 = make_float4(pr1[3], pr1[4], pr1[5], pr1[6]);

    float4 qi = make_float4(-q0.x, -q0.y, -q0.z, q0.w);
    float3 dt = f3(t1.x - t0.x, t1.y - t0.y, t1.z - t0.z);
    float3 t  = qrot(qi, dt);
    float4 q  = qmul(qi, q1);

    float n2 = q.x * q.x + q.y * q.y + q.z * q.z;
    bool small = n2 < 1e-12f;
    float ns = small ? 1.0f : n2;
    float rn = rsqrtf(ns);
    float n  = ns * rn;
    float factor;
    if (small) {
        float iw = __fdividef(1.0f, q.w);
        factor = 2.0f * iw - (2.0f / 3.0f) * n2 * iw * iw * iw;
    } else {
        factor = 2.0f * atan2f(n, q.w) * rn;
    }
    float3 phi = f3(factor * q.x, factor * q.y, factor * q.z);

    float t2 = dot3(phi, phi);
    bool sm2 = t2 < 1e-12f;
    float t2s = sm2 ? 1.0f : t2;
    float rth = rsqrtf(t2s);
    float theta = t2s * rth;
    float s, cth;
    __sincosf(theta, &s, &cth);
    float s_safe = (fabsf(s) < 1e-6f) ? 1e-6f : s;
    float c;
    if (sm2) {
        c = (1.0f / 12.0f) + t2 * (1.0f / 720.0f);
    } else {
        c = rth * rth - __fdividef(1.0f + cth, 2.0f * theta * s_safe);
    }
    float3 x1 = cross3(phi, t);
    float3 x2 = cross3(phi, x1);
    float3 tau = f3(t.x - 0.5f * x1.x + c * x2.x,
                    t.y - 0.5f * x1.y + c * x2.y,
                    t.z - 0.5f * x1.z + c * x2.z);

    float nd2 = dot3(phi, phi);
    if (nd2 < 1e-24f) {
        o[0] = make_float4(tau.x, tau.y, tau.z, 0.f);
        o[1] = make_float4(0.f, 0.f, 0.f, 0.f);
        o[2] = make_float4(0.f, 0.f, 0.f, 0.f);
        o[3] = make_float4(0.f, t0.x, t0.y, t0.z);
        return;
    }
    float rnd = rsqrtf(nd2);
    float nd  = nd2 * rnd;
    float K2  = 2.0f * rnd * rnd;
    float rn3 = rnd * rnd * rnd;
    float3 U  = f3(phi.x * rnd, phi.y * rnd, phi.z * rnd);
    float3 C1 = cross3(phi, tau);
    float3 C2 = cross3(phi, C1);
    C1.x *= K2;  C1.y *= K2;  C1.z *= K2;
    C2.x *= rn3; C2.y *= rn3; C2.z *= rn3;
    o[0] = make_float4(tau.x, tau.y, tau.z, nd);
    o[1] = make_float4(U.x, U.y, U.z, C1.x);
    o[2] = make_float4(C1.y, C1.z, C2.x, C2.y);
    o[3] = make_float4(C2.z, t0.x, t0.y, t0.z);
}

// ---------------------------------------------------------------------------
// Packed transform state (two samples per thread)
// ---------------------------------------------------------------------------
struct X2 { u64 tx, ty, tz, qx, qy, qz, qw; };

// Dup-record u64 slot map (record = 20 u64 = 10 ulonglong2):
//  0:tau.x 1:tau.y 2:tau.z 3:nd   4:U.x 5:U.y 6:U.z 7:C1x
//  8:C1y 9:C1z 10:C2x 11:C2y    12:C2z 13:pt.x 14:pt.y 15:pt.z
// 16:q.x 17:q.y 18:q.z 19:q.w
__device__ __forceinline__ void stepp(X2& T, const ulonglong2* __restrict__ D2,
                                      u64 W) {
    ulonglong2 v1 = D2[1];                       // tau.z | nd
    u64 th = f2mul(W, v1.y);
    float tha, thb; unpk2(th, tha, thb);
    float sa, ca, sb, cb;
    __sincosf(0.5f * tha, &sa, &ca);
    __sincosf(0.5f * thb, &sb, &cb);
    u64 sh = pk2(sa, sb), ch = pk2(ca, cb);
    u64 alpha = f2mul(sh, sh);                          // K2-premult
    u64 beta  = f2fma(f2neg(f2add(sh, sh)), ch, th);    // rn3-premult
    ulonglong2 v0 = D2[0];                       // tau.x | tau.y
    ulonglong2 v3 = D2[3];                       // U.z | C1x
    ulonglong2 v4 = D2[4];                       // C1y | C1z
    ulonglong2 v5 = D2[5];                       // C2x | C2y
    ulonglong2 v6 = D2[6];                       // C2z | pt.x
    u64 Atx = f2fma(beta, v5.x, f2fma(alpha, v3.y, f2mul(W, v0.x)));
    u64 Aty = f2fma(beta, v5.y, f2fma(alpha, v4.x, f2mul(W, v0.y)));
    u64 Atz = f2fma(beta, v6.x, f2fma(alpha, v4.y, f2mul(W, v1.x)));
    ulonglong2 v2 = D2[2];                       // U.x | U.y
    u64 Aqx = f2mul(sh, v2.x);
    u64 Aqy = f2mul(sh, v2.y);
    u64 Aqz = f2mul(sh, v3.x);
    u64 Aqw = ch;

    // T = T * A
    u64 nx = f2neg(T.qx), ny = f2neg(T.qy), nz = f2neg(T.qz);
    u64 cx = f2fma(T.qy, Atz, f2mul(nz, Aty));
    u64 cy = f2fma(T.qz, Atx, f2mul(nx, Atz));
    u64 cz = f2fma(T.qx, Aty, f2mul(ny, Atx));
    cx = f2add(cx, cx); cy = f2add(cy, cy); cz = f2add(cz, cz);
    u64 dx = f2fma(T.qy, cz, f2mul(nz, cy));
    u64 dy = f2fma(T.qz, cx, f2mul(nx, cz));
    u64 dz = f2fma(T.qx, cy, f2mul(ny, cx));
    T.tx = f2add(T.tx, f2add(Atx, f2fma(T.qw, cx, dx)));
    T.ty = f2add(T.ty, f2add(Aty, f2fma(T.qw, cy, dy)));
    T.tz = f2add(T.tz, f2add(Atz, f2fma(T.qw, cz, dz)));
    u64 rqx = f2fma(T.qw, Aqx, f2fma(T.qx, Aqw, f2fma(T.qy, Aqz, f2mul(nz, Aqy))));
    u64 rqy = f2fma(T.qw, Aqy, f2fma(T.qy, Aqw, f2fma(T.qz, Aqx, f2mul(nx, Aqz))));
    u64 rqz = f2fma(T.qw, Aqz, f2fma(T.qz, Aqw, f2fma(T.qx, Aqy, f2mul(ny, Aqx))));
    u64 rqw = f2fma(T.qw, Aqw, f2fma(nx, Aqx, f2fma(ny, Aqy, f2mul(nz, Aqz))));
    T.qx = rqx; T.qy = rqy; T.qz = rqz; T.qw = rqw;
}

__device__ __forceinline__ void unstage(const X2& T, float* smw, unsigned k) {
    float va, vb;
    unsigned oA = k * 7, oB = oA + 112;
    unpk2(T.tx, va, vb); smw[oA + 0] = va; smw[oB + 0] = vb;
    unpk2(T.ty, va, vb); smw[oA + 1] = va; smw[oB + 1] = vb;
    unpk2(T.tz, va, vb); smw[oA + 2] = va; smw[oB + 2] = vb;
    unpk2(T.qx, va, vb); smw[oA + 3] = va; smw[oB + 3] = vb;
    unpk2(T.qy, va, vb); smw[oA + 4] = va; smw[oB + 4] = vb;
    unpk2(T.qz, va, vb); smw[oA + 5] = va; smw[oB + 5] = vb;
    unpk2(T.qw, va, vb); smw[oA + 6] = va; smw[oB + 6] = vb;
}

// ---------------------------------------------------------------------------
// Kernel 2: warp = 4 segments (s0..s0+3); dual packed chains per thread.
// ---------------------------------------------------------------------------
__global__ void __launch_bounds__(256) k_spline(const float* __restrict__ timev,
                                                float* __restrict__ out) {
    __shared__ __align__(16) u64   recd[8 * 120];  // 6 records x 20 dup-u64
    __shared__ __align__(16) float stg[8 * 896];   // 4 x 224 floats per warp

    unsigned w    = threadIdx.x >> 5;
    unsigned lane = threadIdx.x & 31;
    unsigned gp = blockIdx.x * 8 + w;
    if (gp >= LS_B * LS_M4) return;
    unsigned b = gp >> 9;
    unsigned m = gp & (LS_M4 - 1);
    unsigned s0 = 4 * m;
    unsigned nvalid = LS_S - s0;
    if (nvalid > 4) nvalid = 4;

    // ---- cooperative load of records s0..s0+5, duplicated per scalar ----
    u64* rd = recd + w * 120;
    {
        unsigned gbase = (b * LS_J + s0) * REC;
        const unsigned GMAX = LS_B * LS_J * REC - 1;
        unsigned gidx = gbase + lane;
        if (gidx > GMAX) gidx = GMAX;        // tail clamp (unused results)
        if (lane < 30) {
            float4 v = g_pre[gidx];
            ulonglong2* d = (ulonglong2*)(rd + lane * 4);
            d[0] = make_ulonglong2(pk2(v.x, v.x), pk2(v.y, v.y));
            d[1] = make_ulonglong2(pk2(v.z, v.z), pk2(v.w, v.w));
        }
    }
    __syncwarp();

    unsigned half = lane >> 4;     // chain A: segment s0+half; B: s0+2+half
    unsigned k    = lane & 15;     // sample pair (k, k+16)

    // packed spline weights for the two samples
    float ua = __ldg(timev + k);
    float ub = __ldg(timev + k + 16);
    float ua2 = ua * ua, ua3 = ua2 * ua;
    float ub2 = ub * ub, ub3 = ub2 * ub;
    u64 W0 = pk2((5.0f + 3.0f * ua - 3.0f * ua2 + ua3) * (1.0f / 6.0f),
                 (5.0f + 3.0f * ub - 3.0f * ub2 + ub3) * (1.0f / 6.0f));
    u64 W1 = pk2((1.0f + 3.0f * ua + 3.0f * ua2 - 2.0f * ua3) * (1.0f / 6.0f),
                 (1.0f + 3.0f * ub + 3.0f * ub2 - 2.0f * ub3) * (1.0f / 6.0f));
    u64 W2 = pk2(ua3 * (1.0f / 6.0f), ub3 * (1.0f / 6.0f));

    const u64* Da = rd + half * 20;         // records half, half+1, half+2
    const u64* Db = rd + (half + 2) * 20;   // records half+2, half+3, half+4

    X2 Ta, Tb;
    Ta.tx = Da[13]; Ta.ty = Da[14]; Ta.tz = Da[15];
    Ta.qx = Da[16]; Ta.qy = Da[17]; Ta.qz = Da[18]; Ta.qw = Da[19];
    Tb.tx = Db[13]; Tb.ty = Db[14]; Tb.tz = Db[15];
    Tb.qx = Db[16]; Tb.qy = Db[17]; Tb.qz = Db[18]; Tb.qw = Db[19];

    // interleaved independent chains (ILP)
    stepp(Ta, (const ulonglong2*)Da,        W0);
    stepp(Tb, (const ulonglong2*)Db,        W0);
    stepp(Ta, (const ulonglong2*)(Da + 20), W1);
    stepp(Tb, (const ulonglong2*)(Db + 20), W1);
    stepp(Ta, (const ulonglong2*)(Da + 40), W2);
    stepp(Tb, (const ulonglong2*)(Db + 40), W2);

    // ---- staging: unpack both chains into the warp's 896-float block
    float* base = stg + w * 896;
    unstage(Ta, base + half * 224, k);
    unstage(Tb, base + (half + 2) * 224, k);
    __syncwarp();

    // ---- coalesced store
    const float4* sm4 = (const float4*)base;
    unsigned pair0 = b * LS_S + s0;
    float4* ob4 = (float4*)(out) + pair0 * 56;
    unsigned nf4 = nvalid * 56;              // 224 full, 168 tail
#pragma unroll 7
    for (unsigned i = lane; i < nf4; i += 32)
        ob4[i] = sm4[i];
}

extern "C" void kernel_launch(void* const* d_in, const int* in_sizes, int n_in,
                              void* d_out, int out_size) {
    (void)n_in; (void)out_size;
    const float* poses = (const float*)d_in[0];
    const float* timev = (const float*)d_in[1];
    float* out = (float*)d_out;

    int tot1 = LS_B * LS_J;
    k_delta<<<(tot1 + 127) / 128, 128>>>(poses);

    int tot2 = LS_B * LS_M4;   // 16384 warps
    k_spline<<<(tot2 + 7) / 8, 256>>>(timev, out);
}

// round 15
// speedup vs baseline: 1.0438x; 1.0438x over previous
#include <cuda_runtime.h>

// ---------------------------------------------------------------------------
// LieSpline: SE(3) cubic B-spline.  B=32, N=2048, K=32.
//
// Kernel 1: per padded delta j: se3_log + exp precomputes + pose -> g_pre,
//   5 float4/record: r0=(tau|nd) r1=(U|C1'x) r2=(C1'y,C1'z,C2'x,C2'y)
//                    r3=(C2'z,pose_t) r4=pose_q
// Kernel 2 (R13 + wide LDS): warp = 2 segments; lanes 0-15 -> seg s0,
//   lanes 16-31 -> seg s0+1; each lane evaluates samples (k, k+16) packed
//   in f32x2.  Records stored in smem PRE-DUPLICATED (scalar -> (x,x) u64)
//   and read as ulonglong2 (LDS.128): 25 shared loads/thread instead of 46.
//   Single packed chain per thread (small live set, regs ~62).
// ---------------------------------------------------------------------------

#define LS_B 32
#define LS_N 2048
#define LS_J (LS_N + 1)   // 2049 deltas per batch
#define REC 5             // float4s per record in g_pre
#define LS_S (LS_N - 1)   // 2047 segments
#define LS_M 1024         // segment-pairs per batch

__device__ float4 g_pre[LS_B * LS_J * REC];   // 5.2 MB scratch

typedef unsigned long long u64;

__device__ __forceinline__ float3 f3(float x, float y, float z) {
    return make_float3(x, y, z);
}
__device__ __forceinline__ float3 cross3(const float3 a, const float3 b) {
    return make_float3(a.y * b.z - a.z * b.y,
                       a.z * b.x - a.x * b.z,
                       a.x * b.y - a.y * b.x);
}
__device__ __forceinline__ float dot3(const float3 a, const float3 b) {
    return a.x * b.x + a.y * b.y + a.z * b.z;
}
__device__ __forceinline__ float3 qrot(const float4 q, const float3 v) {
    float3 qv = f3(q.x, q.y, q.z);
    float3 t = cross3(qv, v);
    t.x *= 2.0f; t.y *= 2.0f; t.z *= 2.0f;
    float3 c = cross3(qv, t);
    return f3(v.x + q.w * t.x + c.x,
              v.y + q.w * t.y + c.y,
              v.z + q.w * t.z + c.z);
}
__device__ __forceinline__ float4 qmul(const float4 a, const float4 b) {
    return make_float4(
        a.w * b.x + a.x * b.w + a.y * b.z - a.z * b.y,
        a.w * b.y + a.y * b.w + a.z * b.x - a.x * b.z,
        a.w * b.z + a.z * b.w + a.x * b.y - a.y * b.x,
        a.w * b.w - a.x * b.x - a.y * b.y - a.z * b.z);
}

// ---------------- packed f32x2 helpers ----------------
__device__ __forceinline__ u64 pk2(float lo, float hi) {
    u64 r; asm("mov.b64 %0, {%1, %2};" : "=l"(r) : "f"(lo), "f"(hi)); return r;
}
__device__ __forceinline__ void unpk2(u64 v, float& lo, float& hi) {
    asm("mov.b64 {%0, %1}, %2;" : "=f"(lo), "=f"(hi) : "l"(v));
}
__device__ __forceinline__ u64 f2mul(u64 a, u64 b) {
    u64 r; asm("mul.rn.f32x2 %0, %1, %2;" : "=l"(r) : "l"(a), "l"(b)); return r;
}
__device__ __forceinline__ u64 f2add(u64 a, u64 b) {
    u64 r; asm("add.rn.f32x2 %0, %1, %2;" : "=l"(r) : "l"(a), "l"(b)); return r;
}
__device__ __forceinline__ u64 f2fma(u64 a, u64 b, u64 c) {
    u64 r; asm("fma.rn.f32x2 %0, %1, %2, %3;" : "=l"(r) : "l"(a), "l"(b), "l"(c)); return r;
}
__device__ __forceinline__ u64 f2neg(u64 a) { return a ^ 0x8000000080000000ULL; }

// ---------------------------------------------------------------------------
// Kernel 1: per-(b, j) relative-pose log + precompute
// ---------------------------------------------------------------------------
__global__ void __launch_bounds__(128) k_delta(const float* __restrict__ poses) {
    unsigned idx = blockIdx.x * blockDim.x + threadIdx.x;
    if (idx >= LS_B * LS_J) return;
    unsigned b = idx / LS_J;
    unsigned j = idx - b * LS_J;
    float4* o = g_pre + idx * REC;
    const float* pbase = poses + b * (LS_N * 7);

    unsigned pj = j > 0 ? j - 1 : 0;
    const float* pr = pbase + pj * 7;
    float3 t0 = f3(pr[0], pr[1], pr[2]);
    float4 q0 = make_float4(pr[3], pr[4], pr[5], pr[6]);
    o[4] = q0;

    if (j == 0 || j == LS_N) {
        float4 z = make_float4(0.f, 0.f, 0.f, 0.f);
        o[0] = z; o[1] = z; o[2] = z;
        o[3] = make_float4(0.f, t0.x, t0.y, t0.z);
        return;
    }
    const float* pr1 = pr + 7;
    float3 t1 = f3(pr1[0], pr1[1], pr1[2]);
    float4 q1 = make_float4(pr1[3], pr1[4], pr1[5], pr1[6]);

    float4 qi = make_float4(-q0.x, -q0.y, -q0.z, q0.w);
    float3 dt = f3(t1.x - t0.x, t1.y - t0.y, t1.z - t0.z);
    float3 t  = qrot(qi, dt);
    float4 q  = qmul(qi, q1);

    float n2 = q.x * q.x + q.y * q.y + q.z * q.z;
    bool small = n2 < 1e-12f;
    float ns = small ? 1.0f : n2;
    float rn = rsqrtf(ns);
    float n  = ns * rn;
    float factor;
    if (small) {
        float iw = __fdividef(1.0f, q.w);
        factor = 2.0f * iw - (2.0f / 3.0f) * n2 * iw * iw * iw;
    } else {
        factor = 2.0f * atan2f(n, q.w) * rn;
    }
    float3 phi = f3(factor * q.x, factor * q.y, factor * q.z);

    float t2 = dot3(phi, phi);
    bool sm2 = t2 < 1e-12f;
    float t2s = sm2 ? 1.0f : t2;
    float rth = rsqrtf(t2s);
    float theta = t2s * rth;
    float s, cth;
    __sincosf(theta, &s, &cth);
    float s_safe = (fabsf(s) < 1e-6f) ? 1e-6f : s;
    float c;
    if (sm2) {
        c = (1.0f / 12.0f) + t2 * (1.0f / 720.0f);
    } else {
        c = rth * rth - __fdividef(1.0f + cth, 2.0f * theta * s_safe);
    }
    float3 x1 = cross3(phi, t);
    float3 x2 = cross3(phi, x1);
    float3 tau = f3(t.x - 0.5f * x1.x + c * x2.x,
                    t.y - 0.5f * x1.y + c * x2.y,
                    t.z - 0.5f * x1.z + c * x2.z);

    float nd2 = dot3(phi, phi);
    if (nd2 < 1e-24f) {
        o[0] = make_float4(tau.x, tau.y, tau.z, 0.f);
        o[1] = make_float4(0.f, 0.f, 0.f, 0.f);
        o[2] = make_float4(0.f, 0.f, 0.f, 0.f);
        o[3] = make_float4(0.f, t0.x, t0.y, t0.z);
        return;
    }
    float rnd = rsqrtf(nd2);
    float nd  = nd2 * rnd;
    float K2  = 2.0f * rnd * rnd;
    float rn3 = rnd * rnd * rnd;
    float3 U  = f3(phi.x * rnd, phi.y * rnd, phi.z * rnd);
    float3 C1 = cross3(phi, tau);
    float3 C2 = cross3(phi, C1);
    C1.x *= K2;  C1.y *= K2;  C1.z *= K2;
    C2.x *= rn3; C2.y *= rn3; C2.z *= rn3;
    o[0] = make_float4(tau.x, tau.y, tau.z, nd);
    o[1] = make_float4(U.x, U.y, U.z, C1.x);
    o[2] = make_float4(C1.y, C1.z, C2.x, C2.y);
    o[3] = make_float4(C2.z, t0.x, t0.y, t0.z);
}

// ---------------------------------------------------------------------------
// Packed transform state (two samples per thread)
// ---------------------------------------------------------------------------
struct X2 { u64 tx, ty, tz, qx, qy, qz, qw; };

// Dup-record u64 slot map (record = 20 u64 = 10 ulonglong2):
//  0:tau.x 1:tau.y 2:tau.z 3:nd   4:U.x 5:U.y 6:U.z 7:C1x
//  8:C1y 9:C1z 10:C2x 11:C2y    12:C2z 13:pt.x 14:pt.y 15:pt.z
// 16:q.x 17:q.y 18:q.z 19:q.w
__device__ __forceinline__ void stepp(X2& T, const ulonglong2* __restrict__ D2,
                                      u64 W) {
    ulonglong2 v1 = D2[1];                       // tau.z | nd
    u64 th = f2mul(W, v1.y);
    float tha, thb; unpk2(th, tha, thb);
    float sa, ca, sb, cb;
    __sincosf(0.5f * tha, &sa, &ca);
    __sincosf(0.5f * thb, &sb, &cb);
    u64 sh = pk2(sa, sb), ch = pk2(ca, cb);
    u64 alpha = f2mul(sh, sh);                          // K2-premult
    u64 beta  = f2fma(f2neg(f2add(sh, sh)), ch, th);    // rn3-premult
    ulonglong2 v0 = D2[0];                       // tau.x | tau.y
    ulonglong2 v3 = D2[3];                       // U.z | C1x
    ulonglong2 v4 = D2[4];                       // C1y | C1z
    ulonglong2 v5 = D2[5];                       // C2x | C2y
    ulonglong2 v6 = D2[6];                       // C2z | pt.x
    u64 Atx = f2fma(beta, v5.x, f2fma(alpha, v3.y, f2mul(W, v0.x)));
    u64 Aty = f2fma(beta, v5.y, f2fma(alpha, v4.x, f2mul(W, v0.y)));
    u64 Atz = f2fma(beta, v6.x, f2fma(alpha, v4.y, f2mul(W, v1.x)));
    ulonglong2 v2 = D2[2];                       // U.x | U.y
    u64 Aqx = f2mul(sh, v2.x);
    u64 Aqy = f2mul(sh, v2.y);
    u64 Aqz = f2mul(sh, v3.x);
    u64 Aqw = ch;

    // T = T * A
    u64 nx = f2neg(T.qx), ny = f2neg(T.qy), nz = f2neg(T.qz);
    u64 cx = f2fma(T.qy, Atz, f2mul(nz, Aty));
    u64 cy = f2fma(T.qz, Atx, f2mul(nx, Atz));
    u64 cz = f2fma(T.qx, Aty, f2mul(ny, Atx));
    cx = f2add(cx, cx); cy = f2add(cy, cy); cz = f2add(cz, cz);
    u64 dx = f2fma(T.qy, cz, f2mul(nz, cy));
    u64 dy = f2fma(T.qz, cx, f2mul(nx, cz));
    u64 dz = f2fma(T.qx, cy, f2mul(ny, cx));
    T.tx = f2add(T.tx, f2add(Atx, f2fma(T.qw, cx, dx)));
    T.ty = f2add(T.ty, f2add(Aty, f2fma(T.qw, cy, dy)));
    T.tz = f2add(T.tz, f2add(Atz, f2fma(T.qw, cz, dz)));
    u64 rqx = f2fma(T.qw, Aqx, f2fma(T.qx, Aqw, f2fma(T.qy, Aqz, f2mul(nz, Aqy))));
    u64 rqy = f2fma(T.qw, Aqy, f2fma(T.qy, Aqw, f2fma(T.qz, Aqx, f2mul(nx, Aqz))));
    u64 rqz = f2fma(T.qw, Aqz, f2fma(T.qz, Aqw, f2fma(T.qx, Aqy, f2mul(ny, Aqx))));
    u64 rqw = f2fma(T.qw, Aqw, f2fma(nx, Aqx, f2fma(ny, Aqy, f2mul(nz, Aqz))));
    T.qx = rqx; T.qy = rqy; T.qz = rqz; T.qw = rqw;
}

// ---------------------------------------------------------------------------
// Kernel 2: warp = 2 segments; lanes 0-15 seg s0, lanes 16-31 seg s0+1;
// each lane evaluates samples (k, k+16) packed.
// ---------------------------------------------------------------------------
__global__ void __launch_bounds__(256) k_spline(const float* __restrict__ timev,
                                                float* __restrict__ out) {
    __shared__ __align__(16) u64   recd[8 * 80];   // 4 records x 20 dup-u64
    __shared__ __align__(16) float stg[8 * 448];

    unsigned w    = threadIdx.x >> 5;
    unsigned lane = threadIdx.x & 31;
    unsigned gp = blockIdx.x * 8 + w;
    if (gp >= LS_B * LS_M) return;
    unsigned b = gp >> 10;
    unsigned m = gp & (LS_M - 1);
    unsigned s0 = 2 * m;
    bool tail = (s0 + 1 >= LS_S);

    // ---- cooperative load of records s0..s0+3, duplicated per scalar ----
    u64* rd = recd + w * 80;
    {
        unsigned gbase = (b * LS_J + s0) * REC;
        const unsigned GMAX = LS_B * LS_J * REC - 1;
        unsigned gidx = gbase + lane;
        if (gidx > GMAX) gidx = GMAX;        // tail clamp (unused results)
        if (lane < 20) {
            float4 v = g_pre[gidx];
            ulonglong2* d = (ulonglong2*)(rd + lane * 4);
            d[0] = make_ulonglong2(pk2(v.x, v.x), pk2(v.y, v.y));
            d[1] = make_ulonglong2(pk2(v.z, v.z), pk2(v.w, v.w));
        }
    }
    __syncwarp();

    unsigned half = lane >> 4;     // 0: segment s0, 1: segment s0+1
    unsigned k    = lane & 15;     // sample pair (k, k+16)

    // packed spline weights for the two samples
    float ua = __ldg(timev + k);
    float ub = __ldg(timev + k + 16);
    float ua2 = ua * ua, ua3 = ua2 * ua;
    float ub2 = ub * ub, ub3 = ub2 * ub;
    u64 W0 = pk2((5.0f + 3.0f * ua - 3.0f * ua2 + ua3) * (1.0f / 6.0f),
                 (5.0f + 3.0f * ub - 3.0f * ub2 + ub3) * (1.0f / 6.0f));
    u64 W1 = pk2((1.0f + 3.0f * ua + 3.0f * ua2 - 2.0f * ua3) * (1.0f / 6.0f),
                 (1.0f + 3.0f * ub + 3.0f * ub2 - 2.0f * ub3) * (1.0f / 6.0f));
    u64 W2 = pk2(ua3 * (1.0f / 6.0f), ub3 * (1.0f / 6.0f));

    const u64* D = rd + half * 20;   // record s0+half (uniform per half-warp)
    const ulonglong2* D2 = (const ulonglong2*)D;

    // T = pose (dup scalars read wide: pt.y|pt.z, qx|qy, qz|qw, pt.x from v6.y)
    X2 T;
    {
        ulonglong2 p6 = D2[6];   // C2z | pt.x
        ulonglong2 p7 = D2[7];   // pt.y | pt.z
        ulonglong2 p8 = D2[8];   // q.x | q.y
        ulonglong2 p9 = D2[9];   // q.z | q.w
        T.tx = p6.y; T.ty = p7.x; T.tz = p7.y;
        T.qx = p8.x; T.qy = p8.y; T.qz = p9.x; T.qw = p9.y;
    }

    stepp(T, D2,                              W0);
    stepp(T, (const ulonglong2*)(D + 20),     W1);
    stepp(T, (const ulonglong2*)(D + 40),     W2);

    // ---- staging: unpack both samples into the segment's 224-float block
    float* smw = stg + w * 448 + half * 224;
    {
        float va, vb;
        unsigned oA = k * 7, oB = oA + 112;   // (k+16)*7 = k*7 + 112
        unpk2(T.tx, va, vb); smw[oA + 0] = va; smw[oB + 0] = vb;
        unpk2(T.ty, va, vb); smw[oA + 1] = va; smw[oB + 1] = vb;
        unpk2(T.tz, va, vb); smw[oA + 2] = va; smw[oB + 2] = vb;
        unpk2(T.qx, va, vb); smw[oA + 3] = va; smw[oB + 3] = vb;
        unpk2(T.qy, va, vb); smw[oA + 4] = va; smw[oB + 4] = vb;
        unpk2(T.qz, va, vb); smw[oA + 5] = va; smw[oB + 5] = vb;
        unpk2(T.qw, va, vb); smw[oA + 6] = va; smw[oB + 6] = vb;
    }
    __syncwarp();

    // ---- coalesced store: 448 floats (2 segments) or 224 on tail
    const float4* sm4 = (const float4*)(stg + w * 448);
    unsigned pair0 = b * LS_S + s0;
    float4* ob4 = (float4*)(out) + pair0 * 56;
    if (!tail) {
        ob4[lane]      = sm4[lane];
        ob4[lane + 32] = sm4[lane + 32];
        ob4[lane + 64] = sm4[lane + 64];
        if (lane < 16) ob4[lane + 96] = sm4[lane + 96];
    } else {
        ob4[lane] = sm4[lane];
        if (lane < 24) ob4[lane + 32] = sm4[lane + 32];
    }
}

extern "C" void kernel_launch(void* const* d_in, const int* in_sizes, int n_in,
                              void* d_out, int out_size) {
    (void)n_in; (void)out_size;
    const float* poses = (const float*)d_in[0];
    const float* timev = (const float*)d_in[1];
    float* out = (float*)d_out;

    int tot1 = LS_B * LS_J;
    k_delta<<<(tot1 + 127) / 128, 128>>>(poses);

    int tot2 = LS_B * LS_M;   // 32768 warps
    k_spline<<<(tot2 + 7) / 8, 256>>>(timev, out);
}

// round 16
// speedup vs baseline: 1.0774x; 1.0323x over previous
#include <cuda_runtime.h>

// ---------------------------------------------------------------------------
// LieSpline: SE(3) cubic B-spline.  B=32, N=2048, K=32.
//
// Kernel 1: per padded delta j: se3_log + exp precomputes + pose -> g_pre,
//   5 float4/record: r0=(tau|nd) r1=(U|C1'x) r2=(C1'y,C1'z,C2'x,C2'y)
//                    r3=(C2'z,pose_t) r4=pose_q
// Kernel 2 (R13 body, 4 pairs per warp):
//   warp covers 4 consecutive segment-pairs (8 segments) of one batch.
//   ONE cooperative load brings the 10 shared records (50 float4) into smem,
//   duplicated per scalar ((x,x) u64) for pack-free f32x2 operands.
//   Loop over 4 pairs: lanes 0-15 -> even segment, 16-31 -> odd; each lane
//   evaluates samples (k, k+16) packed in f32x2.  Grid 1024 blocks (~1.7
//   waves) amortizes prologue/ramp that capped previous 4096-block variants.
// ---------------------------------------------------------------------------

#define LS_B 32
#define LS_N 2048
#define LS_J (LS_N + 1)   // 2049 deltas per batch
#define REC 5             // float4s per record in g_pre
#define LS_S (LS_N - 1)   // 2047 segments
#define WPB 256           // warps per batch (256 warps x 4 pairs = 1024 pairs)

__device__ float4 g_pre[LS_B * LS_J * REC];   // 5.2 MB scratch

typedef unsigned long long u64;

__device__ __forceinline__ float3 f3(float x, float y, float z) {
    return make_float3(x, y, z);
}
__device__ __forceinline__ float3 cross3(const float3 a, const float3 b) {
    return make_float3(a.y * b.z - a.z * b.y,
                       a.z * b.x - a.x * b.z,
                       a.x * b.y - a.y * b.x);
}
__device__ __forceinline__ float dot3(const float3 a, const float3 b) {
    return a.x * b.x + a.y * b.y + a.z * b.z;
}
__device__ __forceinline__ float3 qrot(const float4 q, const float3 v) {
    float3 qv = f3(q.x, q.y, q.z);
    float3 t = cross3(qv, v);
    t.x *= 2.0f; t.y *= 2.0f; t.z *= 2.0f;
    float3 c = cross3(qv, t);
    return f3(v.x + q.w * t.x + c.x,
              v.y + q.w * t.y + c.y,
              v.z + q.w * t.z + c.z);
}
__device__ __forceinline__ float4 qmul(const float4 a, const float4 b) {
    return make_float4(
        a.w * b.x + a.x * b.w + a.y * b.z - a.z * b.y,
        a.w * b.y + a.y * b.w + a.z * b.x - a.x * b.z,
        a.w * b.z + a.z * b.w + a.x * b.y - a.y * b.x,
        a.w * b.w - a.x * b.x - a.y * b.y - a.z * b.z);
}

// ---------------- packed f32x2 helpers ----------------
__device__ __forceinline__ u64 pk2(float lo, float hi) {
    u64 r; asm("mov.b64 %0, {%1, %2};" : "=l"(r) : "f"(lo), "f"(hi)); return r;
}
__device__ __forceinline__ void unpk2(u64 v, float& lo, float& hi) {
    asm("mov.b64 {%0, %1}, %2;" : "=f"(lo), "=f"(hi) : "l"(v));
}
__device__ __forceinline__ u64 f2mul(u64 a, u64 b) {
    u64 r; asm("mul.rn.f32x2 %0, %1, %2;" : "=l"(r) : "l"(a), "l"(b)); return r;
}
__device__ __forceinline__ u64 f2add(u64 a, u64 b) {
    u64 r; asm("add.rn.f32x2 %0, %1, %2;" : "=l"(r) : "l"(a), "l"(b)); return r;
}
__device__ __forceinline__ u64 f2fma(u64 a, u64 b, u64 c) {
    u64 r; asm("fma.rn.f32x2 %0, %1, %2, %3;" : "=l"(r) : "l"(a), "l"(b), "l"(c)); return r;
}
__device__ __forceinline__ u64 f2neg(u64 a) { return a ^ 0x8000000080000000ULL; }

// ---------------------------------------------------------------------------
// Kernel 1: per-(b, j) relative-pose log + precompute
// ---------------------------------------------------------------------------
__global__ void __launch_bounds__(128) k_delta(const float* __restrict__ poses) {
    unsigned idx = blockIdx.x * blockDim.x + threadIdx.x;
    if (idx >= LS_B * LS_J) return;
    unsigned b = idx / LS_J;
    unsigned j = idx - b * LS_J;
    float4* o = g_pre + idx * REC;
    const float* pbase = poses + b * (LS_N * 7);

    unsigned pj = j > 0 ? j - 1 : 0;
    const float* pr = pbase + pj * 7;
    float3 t0 = f3(pr[0], pr[1], pr[2]);
    float4 q0 = make_float4(pr[3], pr[4], pr[5], pr[6]);
    o[4] = q0;

    if (j == 0 || j == LS_N) {
        float4 z = make_float4(0.f, 0.f, 0.f, 0.f);
        o[0] = z; o[1] = z; o[2] = z;
        o[3] = make_float4(0.f, t0.x, t0.y, t0.z);
        return;
    }
    const float* pr1 = pr + 7;
    float3 t1 = f3(pr1[0], pr1[1], pr1[2]);
    float4 q1 = make_float4(pr1[3], pr1[4], pr1[5], pr1[6]);

    float4 qi = make_float4(-q0.x, -q0.y, -q0.z, q0.w);
    float3 dt = f3(t1.x - t0.x, t1.y - t0.y, t1.z - t0.z);
    float3 t  = qrot(qi, dt);
    float4 q  = qmul(qi, q1);

    float n2 = q.x * q.x + q.y * q.y + q.z * q.z;
    bool small = n2 < 1e-12f;
    float ns = small ? 1.0f : n2;
    float rn = rsqrtf(ns);
    float n  = ns * rn;
    float factor;
    if (small) {
        float iw = __fdividef(1.0f, q.w);
        factor = 2.0f * iw - (2.0f / 3.0f) * n2 * iw * iw * iw;
    } else {
        factor = 2.0f * atan2f(n, q.w) * rn;
    }
    float3 phi = f3(factor * q.x, factor * q.y, factor * q.z);

    float t2 = dot3(phi, phi);
    bool sm2 = t2 < 1e-12f;
    float t2s = sm2 ? 1.0f : t2;
    float rth = rsqrtf(t2s);
    float theta = t2s * rth;
    float s, cth;
    __sincosf(theta, &s, &cth);
    float s_safe = (fabsf(s) < 1e-6f) ? 1e-6f : s;
    float c;
    if (sm2) {
        c = (1.0f / 12.0f) + t2 * (1.0f / 720.0f);
    } else {
        c = rth * rth - __fdividef(1.0f + cth, 2.0f * theta * s_safe);
    }
    float3 x1 = cross3(phi, t);
    float3 x2 = cross3(phi, x1);
    float3 tau = f3(t.x - 0.5f * x1.x + c * x2.x,
                    t.y - 0.5f * x1.y + c * x2.y,
                    t.z - 0.5f * x1.z + c * x2.z);

    float nd2 = dot3(phi, phi);
    if (nd2 < 1e-24f) {
        o[0] = make_float4(tau.x, tau.y, tau.z, 0.f);
        o[1] = make_float4(0.f, 0.f, 0.f, 0.f);
        o[2] = make_float4(0.f, 0.f, 0.f, 0.f);
        o[3] = make_float4(0.f, t0.x, t0.y, t0.z);
        return;
    }
    float rnd = rsqrtf(nd2);
    float nd  = nd2 * rnd;
    float K2  = 2.0f * rnd * rnd;
    float rn3 = rnd * rnd * rnd;
    float3 U  = f3(phi.x * rnd, phi.y * rnd, phi.z * rnd);
    float3 C1 = cross3(phi, tau);
    float3 C2 = cross3(phi, C1);
    C1.x *= K2;  C1.y *= K2;  C1.z *= K2;
    C2.x *= rn3; C2.y *= rn3; C2.z *= rn3;
    o[0] = make_float4(tau.x, tau.y, tau.z, nd);
    o[1] = make_float4(U.x, U.y, U.z, C1.x);
    o[2] = make_float4(C1.y, C1.z, C2.x, C2.y);
    o[3] = make_float4(C2.z, t0.x, t0.y, t0.z);
}

// ---------------------------------------------------------------------------
// Packed transform state (two samples per thread)
// ---------------------------------------------------------------------------
struct X2 { u64 tx, ty, tz, qx, qy, qz, qw; };

// Dup-record u64 slot map (record = 20 u64 = 10 ulonglong2):
//  0:tau.x 1:tau.y 2:tau.z 3:nd   4:U.x 5:U.y 6:U.z 7:C1x
//  8:C1y 9:C1z 10:C2x 11:C2y    12:C2z 13:pt.x 14:pt.y 15:pt.z
// 16:q.x 17:q.y 18:q.z 19:q.w
__device__ __forceinline__ void stepp(X2& T, const ulonglong2* __restrict__ D2,
                                      u64 W) {
    ulonglong2 v1 = D2[1];                       // tau.z | nd
    u64 th = f2mul(W, v1.y);
    float tha, thb; unpk2(th, tha, thb);
    float sa, ca, sb, cb;
    __sincosf(0.5f * tha, &sa, &ca);
    __sincosf(0.5f * thb, &sb, &cb);
    u64 sh = pk2(sa, sb), ch = pk2(ca, cb);
    u64 alpha = f2mul(sh, sh);                          // K2-premult
    u64 beta  = f2fma(f2neg(f2add(sh, sh)), ch, th);    // rn3-premult
    ulonglong2 v0 = D2[0];                       // tau.x | tau.y
    ulonglong2 v3 = D2[3];                       // U.z | C1x
    ulonglong2 v4 = D2[4];                       // C1y | C1z
    ulonglong2 v5 = D2[5];                       // C2x | C2y
    ulonglong2 v6 = D2[6];                       // C2z | pt.x
    u64 Atx = f2fma(beta, v5.x, f2fma(alpha, v3.y, f2mul(W, v0.x)));
    u64 Aty = f2fma(beta, v5.y, f2fma(alpha, v4.x, f2mul(W, v0.y)));
    u64 Atz = f2fma(beta, v6.x, f2fma(alpha, v4.y, f2mul(W, v1.x)));
    ulonglong2 v2 = D2[2];                       // U.x | U.y
    u64 Aqx = f2mul(sh, v2.x);
    u64 Aqy = f2mul(sh, v2.y);
    u64 Aqz = f2mul(sh, v3.x);
    u64 Aqw = ch;

    // T = T * A
    u64 nx = f2neg(T.qx), ny = f2neg(T.qy), nz = f2neg(T.qz);
    u64 cx = f2fma(T.qy, Atz, f2mul(nz, Aty));
    u64 cy = f2fma(T.qz, Atx, f2mul(nx, Atz));
    u64 cz = f2fma(T.qx, Aty, f2mul(ny, Atx));
    cx = f2add(cx, cx); cy = f2add(cy, cy); cz = f2add(cz, cz);
    u64 dx = f2fma(T.qy, cz, f2mul(nz, cy));
    u64 dy = f2fma(T.qz, cx, f2mul(nx, cz));
    u64 dz = f2fma(T.qx, cy, f2mul(ny, cx));
    T.tx = f2add(T.tx, f2add(Atx, f2fma(T.qw, cx, dx)));
    T.ty = f2add(T.ty, f2add(Aty, f2fma(T.qw, cy, dy)));
    T.tz = f2add(T.tz, f2add(Atz, f2fma(T.qw, cz, dz)));
    u64 rqx = f2fma(T.qw, Aqx, f2fma(T.qx, Aqw, f2fma(T.qy, Aqz, f2mul(nz, Aqy))));
    u64 rqy = f2fma(T.qw, Aqy, f2fma(T.qy, Aqw, f2fma(T.qz, Aqx, f2mul(nx, Aqz))));
    u64 rqz = f2fma(T.qw, Aqz, f2fma(T.qz, Aqw, f2fma(T.qx, Aqy, f2mul(ny, Aqx))));
    u64 rqw = f2fma(T.qw, Aqw, f2fma(nx, Aqx, f2fma(ny, Aqy, f2mul(nz, Aqz))));
    T.qx = rqx; T.qy = rqy; T.qz = rqz; T.qw = rqw;
}

// ---------------------------------------------------------------------------
// Kernel 2: warp = 4 consecutive segment-pairs; one coop load of 10 records.
// ---------------------------------------------------------------------------
__global__ void __launch_bounds__(256) k_spline(const float* __restrict__ timev,
                                                float* __restrict__ out) {
    __shared__ __align__(16) u64   recd[8 * 200];  // 10 records x 20 dup-u64
    __shared__ __align__(16) float stg[8 * 448];

    unsigned w    = threadIdx.x >> 5;
    unsigned lane = threadIdx.x & 31;
    unsigned gw   = blockIdx.x * 8 + w;       // global warp id, < 8192
    unsigned b    = gw >> 8;                  // batch
    unsigned wloc = gw & 255;                 // warp within batch
    unsigned segbase = wloc * 8;              // first segment covered

    // ---- cooperative load of records segbase..segbase+9 (50 float4) ----
    u64* rd = recd + w * 200;
    {
        unsigned gbase = (b * LS_J + segbase) * REC;
        const unsigned GMAX = LS_B * LS_J * REC - 1;
        unsigned g0 = gbase + lane;
        if (g0 > GMAX) g0 = GMAX;
        {
            float4 v = g_pre[g0];
            ulonglong2* d = (ulonglong2*)(rd + lane * 4);
            d[0] = make_ulonglong2(pk2(v.x, v.x), pk2(v.y, v.y));
            d[1] = make_ulonglong2(pk2(v.z, v.z), pk2(v.w, v.w));
        }
        if (lane < 18) {
            unsigned g1 = gbase + lane + 32;
            if (g1 > GMAX) g1 = GMAX;
            float4 v = g_pre[g1];
            ulonglong2* d = (ulonglong2*)(rd + (lane + 32) * 4);
            d[0] = make_ulonglong2(pk2(v.x, v.x), pk2(v.y, v.y));
            d[1] = make_ulonglong2(pk2(v.z, v.z), pk2(v.w, v.w));
        }
    }
    __syncwarp();

    unsigned half = lane >> 4;     // 0: even segment of pair, 1: odd
    unsigned k    = lane & 15;     // sample pair (k, k+16)

    // packed spline weights for the two samples (computed ONCE per warp)
    float ua = __ldg(timev + k);
    float ub = __ldg(timev + k + 16);
    float ua2 = ua * ua, ua3 = ua2 * ua;
    float ub2 = ub * ub, ub3 = ub2 * ub;
    u64 W0 = pk2((5.0f + 3.0f * ua - 3.0f * ua2 + ua3) * (1.0f / 6.0f),
                 (5.0f + 3.0f * ub - 3.0f * ub2 + ub3) * (1.0f / 6.0f));
    u64 W1 = pk2((1.0f + 3.0f * ua + 3.0f * ua2 - 2.0f * ua3) * (1.0f / 6.0f),
                 (1.0f + 3.0f * ub + 3.0f * ub2 - 2.0f * ub3) * (1.0f / 6.0f));
    u64 W2 = pk2(ua3 * (1.0f / 6.0f), ub3 * (1.0f / 6.0f));

    float* stw = stg + w * 448;
    const float4* sm4 = (const float4*)stw;

#pragma unroll 1
    for (unsigned it = 0; it < 4; it++) {
        unsigned s0 = segbase + 2 * it;          // even segment of this pair
        bool tail = (s0 + 1 >= LS_S);            // only for wloc=255, it=3

        const u64* D = rd + (2 * it + half) * 20;
        const ulonglong2* D2 = (const ulonglong2*)D;

        // T = pose
        X2 T;
        {
            ulonglong2 p6 = D2[6];   // C2z | pt.x
            ulonglong2 p7 = D2[7];   // pt.y | pt.z
            ulonglong2 p8 = D2[8];   // q.x | q.y
            ulonglong2 p9 = D2[9];   // q.z | q.w
            T.tx = p6.y; T.ty = p7.x; T.tz = p7.y;
            T.qx = p8.x; T.qy = p8.y; T.qz = p9.x; T.qw = p9.y;
        }

        stepp(T, D2,                          W0);
        stepp(T, (const ulonglong2*)(D + 20), W1);
        stepp(T, (const ulonglong2*)(D + 40), W2);

        // stage both samples into the segment's 224-float block
        float* smw = stw + half * 224;
        {
            float va, vb;
            unsigned oA = k * 7, oB = oA + 112;
            unpk2(T.tx, va, vb); smw[oA + 0] = va; smw[oB + 0] = vb;
            unpk2(T.ty, va, vb); smw[oA + 1] = va; smw[oB + 1] = vb;
            unpk2(T.tz, va, vb); smw[oA + 2] = va; smw[oB + 2] = vb;
            unpk2(T.qx, va, vb); smw[oA + 3] = va; smw[oB + 3] = vb;
            unpk2(T.qy, va, vb); smw[oA + 4] = va; smw[oB + 4] = vb;
            unpk2(T.qz, va, vb); smw[oA + 5] = va; smw[oB + 5] = vb;
            unpk2(T.qw, va, vb); smw[oA + 6] = va; smw[oB + 6] = vb;
        }
        __syncwarp();

        // coalesced store: 448 floats (2 segments) or 224 on tail
        float4* ob4 = (float4*)(out) + (b * LS_S + s0) * 56u;
        if (!tail) {
            ob4[lane]      = sm4[lane];
            ob4[lane + 32] = sm4[lane + 32];
            ob4[lane + 64] = sm4[lane + 64];
            if (lane < 16) ob4[lane + 96] = sm4[lane + 96];
        } else {
            ob4[lane] = sm4[lane];
            if (lane < 24) ob4[lane + 32] = sm4[lane + 32];
        }
        __syncwarp();   // staging buffer reused next iteration
    }
}

extern "C" void kernel_launch(void* const* d_in, const int* in_sizes, int n_in,
                              void* d_out, int out_size) {
    (void)n_in; (void)out_size;
    const float* poses = (const float*)d_in[0];
    const float* timev = (const float*)d_in[1];
    float* out = (float*)d_out;

    int tot1 = LS_B * LS_J;
    k_delta<<<(tot1 + 127) / 128, 128>>>(poses);

    // 8192 warps, 8 per block -> 1024 blocks
    k_spline<<<1024, 256>>>(timev, out);
}

// round 17
// speedup vs baseline: 1.1470x; 1.0646x over previous
#include <cuda_runtime.h>

// ---------------------------------------------------------------------------
// LieSpline: SE(3) cubic B-spline.  B=32, N=2048, K=32.  SINGLE FUSED KERNEL.
//
// Warp = 4 consecutive segment-pairs (8 segments) of one batch.
// Warp prologue (lanes 0..9, divergent but issued once per warp): compute the
//   10 delta records this warp needs — se3_log(inv(P[j])P[j+1]) + exp
//   precomputes + base pose — directly into the warp's smem slab in
//   DUPLICATED f32x2 format (each scalar stored as (x,x) u64), 20 u64/record:
//     0:tau.x 1:tau.y 2:tau.z 3:nd   4:U.x 5:U.y 6:U.z 7:C1'x
//     8:C1'y 9:C1'z 10:C2'x 11:C2'y 12:C2'z 13:pt.x 14:pt.y 15:pt.z
//    16:q.x 17:q.y 18:q.z 19:q.w
//   (C1' = (2/nd^2) cross(phi,tau);  C2' = (1/nd^3) cross(phi,cross(phi,tau)))
//   __syncwarp only — no block barrier, no scratch-global round trip.
// Main loop over 4 pairs: lanes 0-15 -> even segment, 16-31 -> odd; each lane
//   evaluates samples (k, k+16) packed in f32x2 (R13/R16-proven body).
// ---------------------------------------------------------------------------

#define LS_B 32
#define LS_N 2048
#define LS_J (LS_N + 1)   // padded delta count per batch
#define LS_S (LS_N - 1)   // 2047 segments

typedef unsigned long long u64;

__device__ __forceinline__ float3 f3(float x, float y, float z) {
    return make_float3(x, y, z);
}
__device__ __forceinline__ float3 cross3(const float3 a, const float3 b) {
    return make_float3(a.y * b.z - a.z * b.y,
                       a.z * b.x - a.x * b.z,
                       a.x * b.y - a.y * b.x);
}
__device__ __forceinline__ float dot3(const float3 a, const float3 b) {
    return a.x * b.x + a.y * b.y + a.z * b.z;
}
__device__ __forceinline__ float3 qrot(const float4 q, const float3 v) {
    float3 qv = f3(q.x, q.y, q.z);
    float3 t = cross3(qv, v);
    t.x *= 2.0f; t.y *= 2.0f; t.z *= 2.0f;
    float3 c = cross3(qv, t);
    return f3(v.x + q.w * t.x + c.x,
              v.y + q.w * t.y + c.y,
              v.z + q.w * t.z + c.z);
}
__device__ __forceinline__ float4 qmul(const float4 a, const float4 b) {
    return make_float4(
        a.w * b.x + a.x * b.w + a.y * b.z - a.z * b.y,
        a.w * b.y + a.y * b.w + a.z * b.x - a.x * b.z,
        a.w * b.z + a.z * b.w + a.x * b.y - a.y * b.x,
        a.w * b.w - a.x * b.x - a.y * b.y - a.z * b.z);
}

// ---------------- packed f32x2 helpers ----------------
__device__ __forceinline__ u64 pk2(float lo, float hi) {
    u64 r; asm("mov.b64 %0, {%1, %2};" : "=l"(r) : "f"(lo), "f"(hi)); return r;
}
__device__ __forceinline__ void unpk2(u64 v, float& lo, float& hi) {
    asm("mov.b64 {%0, %1}, %2;" : "=f"(lo), "=f"(hi) : "l"(v));
}
__device__ __forceinline__ u64 f2mul(u64 a, u64 b) {
    u64 r; asm("mul.rn.f32x2 %0, %1, %2;" : "=l"(r) : "l"(a), "l"(b)); return r;
}
__device__ __forceinline__ u64 f2add(u64 a, u64 b) {
    u64 r; asm("add.rn.f32x2 %0, %1, %2;" : "=l"(r) : "l"(a), "l"(b)); return r;
}
__device__ __forceinline__ u64 f2fma(u64 a, u64 b, u64 c) {
    u64 r; asm("fma.rn.f32x2 %0, %1, %2, %3;" : "=l"(r) : "l"(a), "l"(b), "l"(c)); return r;
}
__device__ __forceinline__ u64 f2neg(u64 a) { return a ^ 0x8000000080000000ULL; }

// ---------------------------------------------------------------------------
// Packed transform state (two samples per thread)
// ---------------------------------------------------------------------------
struct X2 { u64 tx, ty, tz, qx, qy, qz, qw; };

__device__ __forceinline__ void stepp(X2& T, const ulonglong2* __restrict__ D2,
                                      u64 W) {
    ulonglong2 v1 = D2[1];                       // tau.z | nd
    u64 th = f2mul(W, v1.y);
    float tha, thb; unpk2(th, tha, thb);
    float sa, ca, sb, cb;
    __sincosf(0.5f * tha, &sa, &ca);
    __sincosf(0.5f * thb, &sb, &cb);
    u64 sh = pk2(sa, sb), ch = pk2(ca, cb);
    u64 alpha = f2mul(sh, sh);                          // K2-premult
    u64 beta  = f2fma(f2neg(f2add(sh, sh)), ch, th);    // rn3-premult
    ulonglong2 v0 = D2[0];                       // tau.x | tau.y
    ulonglong2 v3 = D2[3];                       // U.z | C1x
    ulonglong2 v4 = D2[4];                       // C1y | C1z
    ulonglong2 v5 = D2[5];                       // C2x | C2y
    ulonglong2 v6 = D2[6];                       // C2z | pt.x
    u64 Atx = f2fma(beta, v5.x, f2fma(alpha, v3.y, f2mul(W, v0.x)));
    u64 Aty = f2fma(beta, v5.y, f2fma(alpha, v4.x, f2mul(W, v0.y)));
    u64 Atz = f2fma(beta, v6.x, f2fma(alpha, v4.y, f2mul(W, v1.x)));
    ulonglong2 v2 = D2[2];                       // U.x | U.y
    u64 Aqx = f2mul(sh, v2.x);
    u64 Aqy = f2mul(sh, v2.y);
    u64 Aqz = f2mul(sh, v3.x);
    u64 Aqw = ch;

    // T = T * A
    u64 nx = f2neg(T.qx), ny = f2neg(T.qy), nz = f2neg(T.qz);
    u64 cx = f2fma(T.qy, Atz, f2mul(nz, Aty));
    u64 cy = f2fma(T.qz, Atx, f2mul(nx, Atz));
    u64 cz = f2fma(T.qx, Aty, f2mul(ny, Atx));
    cx = f2add(cx, cx); cy = f2add(cy, cy); cz = f2add(cz, cz);
    u64 dx = f2fma(T.qy, cz, f2mul(nz, cy));
    u64 dy = f2fma(T.qz, cx, f2mul(nx, cz));
    u64 dz = f2fma(T.qx, cy, f2mul(ny, cx));
    T.tx = f2add(T.tx, f2add(Atx, f2fma(T.qw, cx, dx)));
    T.ty = f2add(T.ty, f2add(Aty, f2fma(T.qw, cy, dy)));
    T.tz = f2add(T.tz, f2add(Atz, f2fma(T.qw, cz, dz)));
    u64 rqx = f2fma(T.qw, Aqx, f2fma(T.qx, Aqw, f2fma(T.qy, Aqz, f2mul(nz, Aqy))));
    u64 rqy = f2fma(T.qw, Aqy, f2fma(T.qy, Aqw, f2fma(T.qz, Aqx, f2mul(nx, Aqz))));
    u64 rqz = f2fma(T.qw, Aqz, f2fma(T.qz, Aqw, f2fma(T.qx, Aqy, f2mul(ny, Aqx))));
    u64 rqw = f2fma(T.qw, Aqw, f2fma(nx, Aqx, f2fma(ny, Aqy, f2mul(nz, Aqz))));
    T.qx = rqx; T.qy = rqy; T.qz = rqz; T.qw = rqw;
}

// ---------------------------------------------------------------------------
// Fused kernel
// ---------------------------------------------------------------------------
__global__ void __launch_bounds__(256)
k_fused(const float* __restrict__ poses,
        const float* __restrict__ timev,
        float* __restrict__ out) {
    __shared__ __align__(16) u64   recd[8 * 200];  // 10 records x 20 dup-u64
    __shared__ __align__(16) float stg[8 * 448];

    unsigned w    = threadIdx.x >> 5;
    unsigned lane = threadIdx.x & 31;
    unsigned gw   = blockIdx.x * 8 + w;       // global warp id, < 8192
    unsigned b    = gw >> 8;                  // batch
    unsigned wloc = gw & 255;                 // warp within batch
    unsigned segbase = wloc * 8;              // first segment covered

    u64* rd = recd + w * 200;
    const float* pbase = poses + b * (LS_N * 7);

    // ---------------- warp prologue: compute 10 records (lanes 0..9) --------
    if (lane < 10) {
        unsigned j = segbase + lane;          // delta index, <= 2049 always
        ulonglong2* o2 = (ulonglong2*)(rd + lane * 20);

        unsigned pj = j > 0 ? j - 1 : 0;
        const float* pr = pbase + pj * 7;
        float3 t0 = f3(pr[0], pr[1], pr[2]);
        float4 q0 = make_float4(pr[3], pr[4], pr[5], pr[6]);

        float3 tau = f3(0.f, 0.f, 0.f);
        float  nd  = 0.f;
        float3 U   = f3(0.f, 0.f, 0.f);
        float3 C1  = f3(0.f, 0.f, 0.f);
        float3 C2  = f3(0.f, 0.f, 0.f);

        if (j != 0 && j != LS_N) {
            const float* pr1 = pr + 7;
            float3 t1 = f3(pr1[0], pr1[1], pr1[2]);
            float4 q1 = make_float4(pr1[3], pr1[4], pr1[5], pr1[6]);

            float4 qi = make_float4(-q0.x, -q0.y, -q0.z, q0.w);
            float3 dt = f3(t1.x - t0.x, t1.y - t0.y, t1.z - t0.z);
            float3 t  = qrot(qi, dt);
            float4 q  = qmul(qi, q1);

            // so3_log
            float n2 = q.x * q.x + q.y * q.y + q.z * q.z;
            bool small = n2 < 1e-12f;
            float ns = small ? 1.0f : n2;
            float rn = rsqrtf(ns);
            float n  = ns * rn;
            float factor;
            if (small) {
                float iw = __fdividef(1.0f, q.w);
                factor = 2.0f * iw - (2.0f / 3.0f) * n2 * iw * iw * iw;
            } else {
                factor = 2.0f * atan2f(n, q.w) * rn;
            }
            float3 phi = f3(factor * q.x, factor * q.y, factor * q.z);

            // jl_inv
            float t2 = dot3(phi, phi);
            bool sm2 = t2 < 1e-12f;
            float t2s = sm2 ? 1.0f : t2;
            float rth = rsqrtf(t2s);
            float theta = t2s * rth;
            float s, cth;
            __sincosf(theta, &s, &cth);
            float s_safe = (fabsf(s) < 1e-6f) ? 1e-6f : s;
            float c;
            if (sm2) {
                c = (1.0f / 12.0f) + t2 * (1.0f / 720.0f);
            } else {
                c = rth * rth - __fdividef(1.0f + cth, 2.0f * theta * s_safe);
            }
            float3 x1 = cross3(phi, t);
            float3 x2 = cross3(phi, x1);
            tau = f3(t.x - 0.5f * x1.x + c * x2.x,
                     t.y - 0.5f * x1.y + c * x2.y,
                     t.z - 0.5f * x1.z + c * x2.z);

            float nd2 = dot3(phi, phi);
            if (nd2 >= 1e-24f) {
                float rnd = rsqrtf(nd2);
                nd  = nd2 * rnd;
                float K2  = 2.0f * rnd * rnd;
                float rn3 = rnd * rnd * rnd;
                U  = f3(phi.x * rnd, phi.y * rnd, phi.z * rnd);
                C1 = cross3(phi, tau);
                C2 = cross3(phi, C1);
                C1.x *= K2;  C1.y *= K2;  C1.z *= K2;
                C2.x *= rn3; C2.y *= rn3; C2.z *= rn3;
            }
        }

        // write dup-format record (10 STS.128)
        o2[0] = make_ulonglong2(pk2(tau.x, tau.x), pk2(tau.y, tau.y));
        o2[1] = make_ulonglong2(pk2(tau.z, tau.z), pk2(nd, nd));
        o2[2] = make_ulonglong2(pk2(U.x, U.x),     pk2(U.y, U.y));
        o2[3] = make_ulonglong2(pk2(U.z, U.z),     pk2(C1.x, C1.x));
        o2[4] = make_ulonglong2(pk2(C1.y, C1.y),   pk2(C1.z, C1.z));
        o2[5] = make_ulonglong2(pk2(C2.x, C2.x),   pk2(C2.y, C2.y));
        o2[6] = make_ulonglong2(pk2(C2.z, C2.z),   pk2(t0.x, t0.x));
        o2[7] = make_ulonglong2(pk2(t0.y, t0.y),   pk2(t0.z, t0.z));
        o2[8] = make_ulonglong2(pk2(q0.x, q0.x),   pk2(q0.y, q0.y));
        o2[9] = make_ulonglong2(pk2(q0.z, q0.z),   pk2(q0.w, q0.w));
    }

    unsigned half = lane >> 4;     // 0: even segment of pair, 1: odd
    unsigned k    = lane & 15;     // sample pair (k, k+16)

    // packed spline weights (independent of prologue -> overlaps it)
    float ua = __ldg(timev + k);
    float ub = __ldg(timev + k + 16);
    float ua2 = ua * ua, ua3 = ua2 * ua;
    float ub2 = ub * ub, ub3 = ub2 * ub;
    u64 W0 = pk2((5.0f + 3.0f * ua - 3.0f * ua2 + ua3) * (1.0f / 6.0f),
                 (5.0f + 3.0f * ub - 3.0f * ub2 + ub3) * (1.0f / 6.0f));
    u64 W1 = pk2((1.0f + 3.0f * ua + 3.0f * ua2 - 2.0f * ua3) * (1.0f / 6.0f),
                 (1.0f + 3.0f * ub + 3.0f * ub2 - 2.0f * ub3) * (1.0f / 6.0f));
    u64 W2 = pk2(ua3 * (1.0f / 6.0f), ub3 * (1.0f / 6.0f));

    __syncwarp();

    float* stw = stg + w * 448;
    const float4* sm4 = (const float4*)stw;

#pragma unroll 1
    for (unsigned it = 0; it < 4; it++) {
        unsigned s0 = segbase + 2 * it;          // even segment of this pair
        bool tail = (s0 + 1 >= LS_S);            // only for wloc=255, it=3

        const u64* D = rd + (2 * it + half) * 20;
        const ulonglong2* D2 = (const ulonglong2*)D;

        // T = pose
        X2 T;
        {
            ulonglong2 p6 = D2[6];   // C2z | pt.x
            ulonglong2 p7 = D2[7];   // pt.y | pt.z
            ulonglong2 p8 = D2[8];   // q.x | q.y
            ulonglong2 p9 = D2[9];   // q.z | q.w
            T.tx = p6.y; T.ty = p7.x; T.tz = p7.y;
            T.qx = p8.x; T.qy = p8.y; T.qz = p9.x; T.qw = p9.y;
        }

        stepp(T, D2,                          W0);
        stepp(T, (const ulonglong2*)(D + 20), W1);
        stepp(T, (const ulonglong2*)(D + 40), W2);

        // stage both samples into the segment's 224-float block
        float* smw = stw + half * 224;
        {
            float va, vb;
            unsigned oA = k * 7, oB = oA + 112;
            unpk2(T.tx, va, vb); smw[oA + 0] = va; smw[oB + 0] = vb;
            unpk2(T.ty, va, vb); smw[oA + 1] = va; smw[oB + 1] = vb;
            unpk2(T.tz, va, vb); smw[oA + 2] = va; smw[oB + 2] = vb;
            unpk2(T.qx, va, vb); smw[oA + 3] = va; smw[oB + 3] = vb;
            unpk2(T.qy, va, vb); smw[oA + 4] = va; smw[oB + 4] = vb;
            unpk2(T.qz, va, vb); smw[oA + 5] = va; smw[oB + 5] = vb;
            unpk2(T.qw, va, vb); smw[oA + 6] = va; smw[oB + 6] = vb;
        }
        __syncwarp();

        // coalesced store: 448 floats (2 segments) or 224 on tail
        float4* ob4 = (float4*)(out) + (b * LS_S + s0) * 56u;
        if (!tail) {
            ob4[lane]      = sm4[lane];
            ob4[lane + 32] = sm4[lane + 32];
            ob4[lane + 64] = sm4[lane + 64];
            if (lane < 16) ob4[lane + 96] = sm4[lane + 96];
        } else {
            ob4[lane] = sm4[lane];
            if (lane < 24) ob4[lane + 32] = sm4[lane + 32];
        }
        __syncwarp();   // staging buffer reused next iteration
    }
}

extern "C" void kernel_launch(void* const* d_in, const int* in_sizes, int n_in,
                              void* d_out, int out_size) {
    (void)n_in; (void)out_size;
    const float* poses = (const float*)d_in[0];
    const float* timev = (const float*)d_in[1];
    float* out = (float*)d_out;

    // 8192 warps (32 batches x 256 warps), 8 per block -> 1024 blocks
    k_fused<<<1024, 256>>>(poses, timev, out);
}